// round 3
// baseline (speedup 1.0000x reference)
#include <cuda_runtime.h>
#include <cuda_bf16.h>
#include <cstdint>
#include <cstddef>

// ============================================================================
// Quantized FFN via exact integer GEMMs:
//   out = quant_linear(relu(quant_linear(x, w1, b1)), w2, b2)
// uint8 act codes x int8 weight codes -> s32 via mma.sync; float epilogue.
// R3: ldmatrix.x4 fragment loads + 3-stage cp.async pipeline, 1 sync/K-tile.
// ============================================================================

#define EPSQ 1e-8f

static constexpr int M_TOT = 8192;
static constexpr int D_DIM = 1024;
static constexpr int F_DIM = 4096;

// ---------------- scratch ----------------------------------------------------
__device__ float g_maxx;
__device__ float g_maxh;
__device__ uint8_t g_qx[(size_t)M_TOT * D_DIM];
__device__ int8_t  g_qw1[(size_t)F_DIM * D_DIM];
__device__ float   g_sw1[F_DIM];
__device__ float   g_scale1[F_DIM];
__device__ float   g_badd1[F_DIM];
__device__ int8_t  g_qw2[(size_t)D_DIM * F_DIM];
__device__ float   g_sw2[D_DIM];
__device__ float   g_h[(size_t)M_TOT * F_DIM];
__device__ uint8_t g_qh[(size_t)M_TOT * F_DIM];

// ---------------- PTX helpers ------------------------------------------------
__device__ __forceinline__ uint32_t smem_u32(const void* p) {
    uint32_t a;
    asm("{ .reg .u64 t; cvta.to.shared.u64 t, %1; cvt.u32.u64 %0, t; }"
        : "=r"(a) : "l"(p));
    return a;
}

__device__ __forceinline__ void cp16(uint32_t dst, const void* src) {
    asm volatile("cp.async.cg.shared.global [%0], [%1], 16;" :: "r"(dst), "l"(src));
}
#define CP_COMMIT() asm volatile("cp.async.commit_group;" ::: "memory")
#define CP_WAIT1()  asm volatile("cp.async.wait_group 1;" ::: "memory")

__device__ __forceinline__ void ldsm4(uint32_t* r, uint32_t addr) {
    asm volatile("ldmatrix.sync.aligned.m8n8.x4.shared.b16 {%0,%1,%2,%3}, [%4];"
        : "=r"(r[0]), "=r"(r[1]), "=r"(r[2]), "=r"(r[3]) : "r"(addr));
}

__device__ __forceinline__ void mma_u8s8(int* c, const uint32_t* a, const uint32_t* b) {
    asm volatile(
        "mma.sync.aligned.m16n8k32.row.col.s32.u8.s8.s32 "
        "{%0,%1,%2,%3}, {%4,%5,%6,%7}, {%8,%9}, {%0,%1,%2,%3};"
        : "+r"(c[0]), "+r"(c[1]), "+r"(c[2]), "+r"(c[3])
        : "r"(a[0]), "r"(a[1]), "r"(a[2]), "r"(a[3]), "r"(b[0]), "r"(b[1]));
}

// ---------------- elementwise / reduction kernels ----------------------------
__global__ void init_kernel() {
    g_maxx = 0.0f;
    g_maxh = 0.0f;
}

__global__ void max_x_kernel(const float* __restrict__ x) {
    float m = 0.0f;
    const int n4 = (M_TOT * D_DIM) / 4;
    for (int i = blockIdx.x * blockDim.x + threadIdx.x; i < n4; i += gridDim.x * blockDim.x) {
        float4 v = reinterpret_cast<const float4*>(x)[i];
        m = fmaxf(m, fmaxf(fmaxf(v.x, v.y), fmaxf(v.z, v.w)));
    }
    #pragma unroll
    for (int o = 16; o; o >>= 1) m = fmaxf(m, __shfl_xor_sync(0xffffffffu, m, o));
    __shared__ float red[8];
    int wid = threadIdx.x >> 5, lid = threadIdx.x & 31;
    if (lid == 0) red[wid] = m;
    __syncthreads();
    if (threadIdx.x == 0) {
        float b = red[0];
        int nw = blockDim.x >> 5;
        for (int i = 1; i < nw; i++) b = fmaxf(b, red[i]);
        atomicMax(reinterpret_cast<unsigned int*>(&g_maxx), __float_as_uint(fmaxf(b, 0.0f)));
    }
}

template <int K, bool W1>
__global__ void scales_w_kernel(const float* __restrict__ w, const float* __restrict__ b1) {
    const int r = blockIdx.x;
    const float4* row = reinterpret_cast<const float4*>(w + (size_t)r * K);
    const int t = threadIdx.x;  // 128
    float m = 0.0f;
    for (int i = t; i < K / 4; i += 128) {
        float4 v = row[i];
        m = fmaxf(m, fmaxf(fmaxf(fabsf(v.x), fabsf(v.y)), fmaxf(fabsf(v.z), fabsf(v.w))));
    }
    #pragma unroll
    for (int o = 16; o; o >>= 1) m = fmaxf(m, __shfl_xor_sync(0xffffffffu, m, o));
    __shared__ float red[4];
    if ((t & 31) == 0) red[t >> 5] = m;
    __syncthreads();
    if (t == 0) {
        float mx = fmaxf(fmaxf(red[0], red[1]), fmaxf(red[2], red[3]));
        float s = __fdiv_rn(fmaxf(mx, EPSQ), 127.0f);
        if (W1) {
            g_sw1[r] = s;
            float s1 = __fdiv_rn(fmaxf(g_maxx, EPSQ), 255.0f);
            float sc = s1 * s;
            g_scale1[r] = sc;
            g_badd1[r] = rintf(__fdiv_rn(b1[r], sc)) * sc;
        } else {
            g_sw2[r] = s;
        }
    }
}

template <int K>
__global__ void quant_w_kernel(const float* __restrict__ w, const float* __restrict__ sw,
                               int8_t* __restrict__ qw, int n_elems) {
    const int n4 = n_elems / 4;
    for (int i = blockIdx.x * blockDim.x + threadIdx.x; i < n4; i += gridDim.x * blockDim.x) {
        float4 v = reinterpret_cast<const float4*>(w)[i];
        float s = sw[(i * 4) / K];
        float q0 = fminf(fmaxf(rintf(__fdiv_rn(v.x, s)), -128.0f), 127.0f);
        float q1 = fminf(fmaxf(rintf(__fdiv_rn(v.y, s)), -128.0f), 127.0f);
        float q2 = fminf(fmaxf(rintf(__fdiv_rn(v.z, s)), -128.0f), 127.0f);
        float q3 = fminf(fmaxf(rintf(__fdiv_rn(v.w, s)), -128.0f), 127.0f);
        char4 o;
        o.x = (char)(int)q0; o.y = (char)(int)q1; o.z = (char)(int)q2; o.w = (char)(int)q3;
        reinterpret_cast<char4*>(qw)[i] = o;
    }
}

__global__ void quant_x_kernel(const float* __restrict__ x) {
    const float s1 = __fdiv_rn(fmaxf(g_maxx, EPSQ), 255.0f);
    const int n4 = (M_TOT * D_DIM) / 4;
    for (int i = blockIdx.x * blockDim.x + threadIdx.x; i < n4; i += gridDim.x * blockDim.x) {
        float4 v = reinterpret_cast<const float4*>(x)[i];
        float q0 = fminf(fmaxf(rintf(__fdiv_rn(v.x, s1)), 0.0f), 255.0f);
        float q1 = fminf(fmaxf(rintf(__fdiv_rn(v.y, s1)), 0.0f), 255.0f);
        float q2 = fminf(fmaxf(rintf(__fdiv_rn(v.z, s1)), 0.0f), 255.0f);
        float q3 = fminf(fmaxf(rintf(__fdiv_rn(v.w, s1)), 0.0f), 255.0f);
        uchar4 o;
        o.x = (unsigned char)(int)q0; o.y = (unsigned char)(int)q1;
        o.z = (unsigned char)(int)q2; o.w = (unsigned char)(int)q3;
        reinterpret_cast<uchar4*>(g_qx)[i] = o;
    }
}

__global__ void quant_h_kernel() {
    const float s2 = __fdiv_rn(fmaxf(g_maxh, EPSQ), 255.0f);
    const size_t n4 = ((size_t)M_TOT * F_DIM) / 4;
    for (size_t i = blockIdx.x * (size_t)blockDim.x + threadIdx.x; i < n4;
         i += (size_t)gridDim.x * blockDim.x) {
        float4 v = reinterpret_cast<const float4*>(g_h)[i];
        float q0 = fminf(fmaxf(rintf(__fdiv_rn(v.x, s2)), 0.0f), 255.0f);
        float q1 = fminf(fmaxf(rintf(__fdiv_rn(v.y, s2)), 0.0f), 255.0f);
        float q2 = fminf(fmaxf(rintf(__fdiv_rn(v.z, s2)), 0.0f), 255.0f);
        float q3 = fminf(fmaxf(rintf(__fdiv_rn(v.w, s2)), 0.0f), 255.0f);
        uchar4 o;
        o.x = (unsigned char)(int)q0; o.y = (unsigned char)(int)q1;
        o.z = (unsigned char)(int)q2; o.w = (unsigned char)(int)q3;
        reinterpret_cast<uchar4*>(g_qh)[i] = o;
    }
}

// ---------------- int8 GEMM --------------------------------------------------
// D[m,n] = sum_k A[m,k]*B[n,k]; CTA 128x128x64; 8 warps 2(M)x4(N), warp 64x32;
// ldmatrix.x4 fragments; 3-stage cp.async pipeline, one sync per K-tile.
static constexpr int TM = 128, TN = 128, TK = 64;
static constexpr int AST = 80;                 // row stride (64 + 16 pad)
static constexpr int HALFB = 128 * AST;        // one operand (128 rows)
static constexpr int STAGEB = 2 * HALFB;       // A + B per stage = 20480
static constexpr int NSTAGE = 3;
static constexpr int GEMM_SMEM = NSTAGE * STAGEB;   // 61440

template <int KTOT, int NTOT, bool G1>
__global__ void __launch_bounds__(256, 2) gemm_imma(float* __restrict__ outp,
                                                    const float* __restrict__ bias)
{
    extern __shared__ __align__(16) unsigned char smem[];
    __shared__ float csc[TN], cbd[TN], wred[8];

    const int tid = threadIdx.x, lane = tid & 31, wid = tid >> 5;
    const int warp_m = wid & 1, warp_n = wid >> 1;
    const int m0 = blockIdx.y * TM, n0 = blockIdx.x * TN;

    const uint8_t* __restrict__ A = G1 ? g_qx : g_qh;
    const int8_t*  __restrict__ B = G1 ? g_qw1 : g_qw2;

    if (tid < TN) {
        int n = n0 + tid;
        if (G1) {
            csc[tid] = g_scale1[n];
            cbd[tid] = g_badd1[n];
        } else {
            float s2 = __fdiv_rn(fmaxf(g_maxh, EPSQ), 255.0f);
            float sc = s2 * g_sw2[n];
            csc[tid] = sc;
            cbd[tid] = rintf(__fdiv_rn(bias[n], sc)) * sc;
        }
    }

    const uint32_t sAddr = smem_u32(smem);
    const int NT = KTOT / TK;
    const int lr = tid >> 2, lkv = tid & 3;

    auto load_tile = [&](int t, int s) {
        const size_t kb = (size_t)t * TK + lkv * 16;
        const uint32_t sb = sAddr + s * STAGEB + lkv * 16;
        #pragma unroll
        for (int it = 0; it < 2; ++it) {
            int r = lr + it * 64;
            cp16(sb + r * AST, A + (size_t)(m0 + r) * KTOT + kb);
            cp16(sb + HALFB + r * AST, B + (size_t)(n0 + r) * KTOT + kb);
        }
    };

    load_tile(0, 0); CP_COMMIT();
    load_tile(1, 1); CP_COMMIT();

    int acc[4][4][4];
    #pragma unroll
    for (int i = 0; i < 4; ++i)
        #pragma unroll
        for (int j = 0; j < 4; ++j)
            #pragma unroll
            for (int k = 0; k < 4; ++k) acc[i][j][k] = 0;

    // per-lane ldmatrix base offsets (within a stage)
    const uint32_t aLane =
        (uint32_t)(warp_m * 64 + (lane & 15)) * AST + (lane >> 4) * 16;
    const uint32_t bLane = HALFB +
        (uint32_t)(warp_n * 32 + ((lane & 7) | ((lane & 16) >> 1))) * AST +
        ((lane >> 3) & 1) * 16;

    int buf = 0;
    for (int t = 0; t < NT; ++t) {
        CP_WAIT1();
        __syncthreads();
        if (t + 2 < NT) {
            int s = buf + 2; if (s >= NSTAGE) s -= NSTAGE;
            load_tile(t + 2, s);
        }
        CP_COMMIT();

        const uint32_t base = sAddr + buf * STAGEB;
        #pragma unroll
        for (int ks = 0; ks < 2; ++ks) {
            uint32_t af[4][4], bf[2][4];
            #pragma unroll
            for (int fm = 0; fm < 4; ++fm)
                ldsm4(af[fm], base + aLane + fm * (16 * AST) + ks * 32);
            #pragma unroll
            for (int fp = 0; fp < 2; ++fp)
                ldsm4(bf[fp], base + bLane + fp * (16 * AST) + ks * 32);
            #pragma unroll
            for (int fm = 0; fm < 4; ++fm)
                #pragma unroll
                for (int fn = 0; fn < 4; ++fn)
                    mma_u8s8(acc[fm][fn], af[fm], &bf[fn >> 1][(fn & 1) * 2]);
        }
        if (++buf == NSTAGE) buf = 0;
    }

    // -------- epilogue -------------------------------------------------------
    float* __restrict__ O = G1 ? g_h : outp;
    float lmax = 0.0f;
    #pragma unroll
    for (int fm = 0; fm < 4; ++fm) {
        const int r0 = m0 + warp_m * 64 + fm * 16 + (lane >> 2);
        #pragma unroll
        for (int fn = 0; fn < 4; ++fn) {
            const int cl = warp_n * 32 + fn * 8 + (lane & 3) * 2;
            const float s0 = csc[cl], s1 = csc[cl + 1];
            const float d0 = cbd[cl], d1 = cbd[cl + 1];
            float v00 = s0 * (float)acc[fm][fn][0] + d0;
            float v01 = s1 * (float)acc[fm][fn][1] + d1;
            float v10 = s0 * (float)acc[fm][fn][2] + d0;
            float v11 = s1 * (float)acc[fm][fn][3] + d1;
            if (G1) {
                v00 = fmaxf(v00, 0.0f); v01 = fmaxf(v01, 0.0f);
                v10 = fmaxf(v10, 0.0f); v11 = fmaxf(v11, 0.0f);
                lmax = fmaxf(lmax, fmaxf(fmaxf(v00, v01), fmaxf(v10, v11)));
            }
            *reinterpret_cast<float2*>(O + (size_t)r0 * NTOT + n0 + cl) =
                make_float2(v00, v01);
            *reinterpret_cast<float2*>(O + (size_t)(r0 + 8) * NTOT + n0 + cl) =
                make_float2(v10, v11);
        }
    }

    if (G1) {
        #pragma unroll
        for (int o = 16; o; o >>= 1) lmax = fmaxf(lmax, __shfl_xor_sync(0xffffffffu, lmax, o));
        if (lane == 0) wred[wid] = lmax;
        __syncthreads();
        if (tid == 0) {
            float b = wred[0];
            #pragma unroll
            for (int i = 1; i < 8; i++) b = fmaxf(b, wred[i]);
            atomicMax(reinterpret_cast<unsigned int*>(&g_maxh), __float_as_uint(b));
        }
    }
}

// ---------------- launcher ---------------------------------------------------
extern "C" void kernel_launch(void* const* d_in, const int* in_sizes, int n_in,
                              void* d_out, int out_size)
{
    const float* x  = (const float*)d_in[0];
    const float* w1 = (const float*)d_in[1];
    const float* b1 = (const float*)d_in[2];
    const float* w2 = (const float*)d_in[3];
    const float* b2 = (const float*)d_in[4];
    float* out = (float*)d_out;

    int8_t* qw1p; cudaGetSymbolAddress((void**)&qw1p, g_qw1);
    int8_t* qw2p; cudaGetSymbolAddress((void**)&qw2p, g_qw2);
    float* sw1p;  cudaGetSymbolAddress((void**)&sw1p, g_sw1);
    float* sw2p;  cudaGetSymbolAddress((void**)&sw2p, g_sw2);

    cudaFuncSetAttribute((const void*)gemm_imma<D_DIM, F_DIM, true>,
                         cudaFuncAttributeMaxDynamicSharedMemorySize, GEMM_SMEM);
    cudaFuncSetAttribute((const void*)gemm_imma<F_DIM, D_DIM, false>,
                         cudaFuncAttributeMaxDynamicSharedMemorySize, GEMM_SMEM);

    init_kernel<<<1, 1>>>();
    max_x_kernel<<<256, 256>>>(x);
    scales_w_kernel<D_DIM, true><<<F_DIM, 128>>>(w1, b1);
    scales_w_kernel<F_DIM, false><<<D_DIM, 128>>>(w2, nullptr);
    quant_w_kernel<D_DIM><<<512, 256>>>(w1, sw1p, qw1p, F_DIM * D_DIM);
    quant_w_kernel<F_DIM><<<512, 256>>>(w2, sw2p, qw2p, D_DIM * F_DIM);
    quant_x_kernel<<<1024, 256>>>(x);
    gemm_imma<D_DIM, F_DIM, true>
        <<<dim3(F_DIM / TN, M_TOT / TM), 256, GEMM_SMEM>>>(nullptr, nullptr);
    quant_h_kernel<<<2048, 256>>>();
    gemm_imma<F_DIM, D_DIM, false>
        <<<dim3(D_DIM / TN, M_TOT / TM), 256, GEMM_SMEM>>>(out, b2);
}

// round 4
// speedup vs baseline: 1.2841x; 1.2841x over previous
#include <cuda_runtime.h>
#include <cuda_bf16.h>
#include <cstdint>
#include <cstddef>

// ============================================================================
// Quantized FFN via exact integer-in-bf16 GEMMs:
//   out = quant_linear(relu(quant_linear(x, w1, b1)), w2, b2)
// Codes (uint8/int8 ranges) stored exactly in bf16; mma.sync bf16 -> f32.
// R4 experiment: HMMA vs IMMA legacy-pipe rate on sm_103.
// ============================================================================

#define EPSQ 1e-8f

static constexpr int M_TOT = 8192;
static constexpr int D_DIM = 1024;
static constexpr int F_DIM = 4096;

// ---------------- scratch ----------------------------------------------------
__device__ float g_maxx;
__device__ float g_maxh;
__device__ __nv_bfloat16 g_qx[(size_t)M_TOT * D_DIM];    // 16 MB
__device__ __nv_bfloat16 g_qw1[(size_t)F_DIM * D_DIM];   // 8 MB
__device__ float g_sw1[F_DIM];
__device__ float g_scale1[F_DIM];
__device__ float g_badd1[F_DIM];
__device__ __nv_bfloat16 g_qw2[(size_t)D_DIM * F_DIM];   // 8 MB
__device__ float g_sw2[D_DIM];
__device__ float g_h[(size_t)M_TOT * F_DIM];             // 128 MB
__device__ __nv_bfloat16 g_qh[(size_t)M_TOT * F_DIM];    // 64 MB

// ---------------- PTX helpers ------------------------------------------------
__device__ __forceinline__ uint32_t smem_u32(const void* p) {
    uint32_t a;
    asm("{ .reg .u64 t; cvta.to.shared.u64 t, %1; cvt.u32.u64 %0, t; }"
        : "=r"(a) : "l"(p));
    return a;
}

__device__ __forceinline__ void cp16(uint32_t dst, const void* src) {
    asm volatile("cp.async.cg.shared.global [%0], [%1], 16;" :: "r"(dst), "l"(src));
}
#define CP_COMMIT() asm volatile("cp.async.commit_group;" ::: "memory")
#define CP_WAIT1()  asm volatile("cp.async.wait_group 1;" ::: "memory")

__device__ __forceinline__ void ldsm4(uint32_t* r, uint32_t addr) {
    asm volatile("ldmatrix.sync.aligned.m8n8.x4.shared.b16 {%0,%1,%2,%3}, [%4];"
        : "=r"(r[0]), "=r"(r[1]), "=r"(r[2]), "=r"(r[3]) : "r"(addr));
}

__device__ __forceinline__ void mma_bf16(float* c, const uint32_t* a, const uint32_t* b) {
    asm volatile(
        "mma.sync.aligned.m16n8k16.row.col.f32.bf16.bf16.f32 "
        "{%0,%1,%2,%3}, {%4,%5,%6,%7}, {%8,%9}, {%0,%1,%2,%3};"
        : "+f"(c[0]), "+f"(c[1]), "+f"(c[2]), "+f"(c[3])
        : "r"(a[0]), "r"(a[1]), "r"(a[2]), "r"(a[3]), "r"(b[0]), "r"(b[1]));
}

// ---------------- elementwise / reduction kernels ----------------------------
__global__ void init_kernel() {
    g_maxx = 0.0f;
    g_maxh = 0.0f;
}

__global__ void max_x_kernel(const float* __restrict__ x) {
    float m = 0.0f;
    const int n4 = (M_TOT * D_DIM) / 4;
    for (int i = blockIdx.x * blockDim.x + threadIdx.x; i < n4; i += gridDim.x * blockDim.x) {
        float4 v = reinterpret_cast<const float4*>(x)[i];
        m = fmaxf(m, fmaxf(fmaxf(v.x, v.y), fmaxf(v.z, v.w)));
    }
    #pragma unroll
    for (int o = 16; o; o >>= 1) m = fmaxf(m, __shfl_xor_sync(0xffffffffu, m, o));
    __shared__ float red[8];
    int wid = threadIdx.x >> 5, lid = threadIdx.x & 31;
    if (lid == 0) red[wid] = m;
    __syncthreads();
    if (threadIdx.x == 0) {
        float b = red[0];
        int nw = blockDim.x >> 5;
        for (int i = 1; i < nw; i++) b = fmaxf(b, red[i]);
        atomicMax(reinterpret_cast<unsigned int*>(&g_maxx), __float_as_uint(fmaxf(b, 0.0f)));
    }
}

template <int K, bool W1>
__global__ void scales_w_kernel(const float* __restrict__ w, const float* __restrict__ b1) {
    const int r = blockIdx.x;
    const float4* row = reinterpret_cast<const float4*>(w + (size_t)r * K);
    const int t = threadIdx.x;  // 128
    float m = 0.0f;
    for (int i = t; i < K / 4; i += 128) {
        float4 v = row[i];
        m = fmaxf(m, fmaxf(fmaxf(fabsf(v.x), fabsf(v.y)), fmaxf(fabsf(v.z), fabsf(v.w))));
    }
    #pragma unroll
    for (int o = 16; o; o >>= 1) m = fmaxf(m, __shfl_xor_sync(0xffffffffu, m, o));
    __shared__ float red[4];
    if ((t & 31) == 0) red[t >> 5] = m;
    __syncthreads();
    if (t == 0) {
        float mx = fmaxf(fmaxf(red[0], red[1]), fmaxf(red[2], red[3]));
        float s = __fdiv_rn(fmaxf(mx, EPSQ), 127.0f);
        if (W1) {
            g_sw1[r] = s;
            float s1 = __fdiv_rn(fmaxf(g_maxx, EPSQ), 255.0f);
            float sc = s1 * s;
            g_scale1[r] = sc;
            g_badd1[r] = rintf(__fdiv_rn(b1[r], sc)) * sc;
        } else {
            g_sw2[r] = s;
        }
    }
}

template <int K>
__global__ void quant_w_kernel(const float* __restrict__ w, const float* __restrict__ sw,
                               __nv_bfloat16* __restrict__ qw, int n_elems) {
    const int n4 = n_elems / 4;
    for (int i = blockIdx.x * blockDim.x + threadIdx.x; i < n4; i += gridDim.x * blockDim.x) {
        float4 v = reinterpret_cast<const float4*>(w)[i];
        float s = sw[(i * 4) / K];
        float q0 = fminf(fmaxf(rintf(__fdiv_rn(v.x, s)), -128.0f), 127.0f);
        float q1 = fminf(fmaxf(rintf(__fdiv_rn(v.y, s)), -128.0f), 127.0f);
        float q2 = fminf(fmaxf(rintf(__fdiv_rn(v.z, s)), -128.0f), 127.0f);
        float q3 = fminf(fmaxf(rintf(__fdiv_rn(v.w, s)), -128.0f), 127.0f);
        __nv_bfloat162 lo = __floats2bfloat162_rn(q0, q1);
        __nv_bfloat162 hi = __floats2bfloat162_rn(q2, q3);
        uint2 pk;
        pk.x = *reinterpret_cast<unsigned int*>(&lo);
        pk.y = *reinterpret_cast<unsigned int*>(&hi);
        reinterpret_cast<uint2*>(qw)[i] = pk;
    }
}

__global__ void quant_x_kernel(const float* __restrict__ x) {
    const float s1 = __fdiv_rn(fmaxf(g_maxx, EPSQ), 255.0f);
    const int n4 = (M_TOT * D_DIM) / 4;
    for (int i = blockIdx.x * blockDim.x + threadIdx.x; i < n4; i += gridDim.x * blockDim.x) {
        float4 v = reinterpret_cast<const float4*>(x)[i];
        float q0 = fminf(fmaxf(rintf(__fdiv_rn(v.x, s1)), 0.0f), 255.0f);
        float q1 = fminf(fmaxf(rintf(__fdiv_rn(v.y, s1)), 0.0f), 255.0f);
        float q2 = fminf(fmaxf(rintf(__fdiv_rn(v.z, s1)), 0.0f), 255.0f);
        float q3 = fminf(fmaxf(rintf(__fdiv_rn(v.w, s1)), 0.0f), 255.0f);
        __nv_bfloat162 lo = __floats2bfloat162_rn(q0, q1);
        __nv_bfloat162 hi = __floats2bfloat162_rn(q2, q3);
        uint2 pk;
        pk.x = *reinterpret_cast<unsigned int*>(&lo);
        pk.y = *reinterpret_cast<unsigned int*>(&hi);
        reinterpret_cast<uint2*>(g_qx)[i] = pk;
    }
}

__global__ void quant_h_kernel() {
    const float s2 = __fdiv_rn(fmaxf(g_maxh, EPSQ), 255.0f);
    const size_t n4 = ((size_t)M_TOT * F_DIM) / 4;
    for (size_t i = blockIdx.x * (size_t)blockDim.x + threadIdx.x; i < n4;
         i += (size_t)gridDim.x * blockDim.x) {
        float4 v = reinterpret_cast<const float4*>(g_h)[i];
        float q0 = fminf(fmaxf(rintf(__fdiv_rn(v.x, s2)), 0.0f), 255.0f);
        float q1 = fminf(fmaxf(rintf(__fdiv_rn(v.y, s2)), 0.0f), 255.0f);
        float q2 = fminf(fmaxf(rintf(__fdiv_rn(v.z, s2)), 0.0f), 255.0f);
        float q3 = fminf(fmaxf(rintf(__fdiv_rn(v.w, s2)), 0.0f), 255.0f);
        __nv_bfloat162 lo = __floats2bfloat162_rn(q0, q1);
        __nv_bfloat162 hi = __floats2bfloat162_rn(q2, q3);
        uint2 pk;
        pk.x = *reinterpret_cast<unsigned int*>(&lo);
        pk.y = *reinterpret_cast<unsigned int*>(&hi);
        reinterpret_cast<uint2*>(g_qh)[i] = pk;
    }
}

// ---------------- bf16 GEMM --------------------------------------------------
// D[m,n] = sum_k A[m,k]*B[n,k]; CTA 128x128x64(bf16); 8 warps 2(M)x4(N),
// warp 64x32; mma m16n8k16 bf16->f32; ldmatrix.x4; 2-stage cp.async.
static constexpr int TM = 128, TN = 128, TK = 64;
static constexpr int AST = 144;                // 128B row + 16B pad
static constexpr int HALFB = 128 * AST;        // 18432
static constexpr int STAGEB = 2 * HALFB;       // 36864
static constexpr int NSTAGE = 2;
static constexpr int GEMM_SMEM = NSTAGE * STAGEB;   // 73728

template <int KTOT, int NTOT, bool G1>
__global__ void __launch_bounds__(256, 2) gemm_hmma(float* __restrict__ outp,
                                                    const float* __restrict__ bias)
{
    extern __shared__ __align__(16) unsigned char smem[];
    __shared__ float csc[TN], cbd[TN], wred[8];

    const int tid = threadIdx.x, lane = tid & 31, wid = tid >> 5;
    const int warp_m = wid & 1, warp_n = wid >> 1;
    const int m0 = blockIdx.y * TM, n0 = blockIdx.x * TN;

    const __nv_bfloat16* __restrict__ A = G1 ? g_qx : g_qh;
    const __nv_bfloat16* __restrict__ B = G1 ? g_qw1 : g_qw2;

    if (tid < TN) {
        int n = n0 + tid;
        if (G1) {
            csc[tid] = g_scale1[n];
            cbd[tid] = g_badd1[n];
        } else {
            float s2 = __fdiv_rn(fmaxf(g_maxh, EPSQ), 255.0f);
            float sc = s2 * g_sw2[n];
            csc[tid] = sc;
            cbd[tid] = rintf(__fdiv_rn(bias[n], sc)) * sc;
        }
    }

    const uint32_t sAddr = smem_u32(smem);
    const int NT = KTOT / TK;
    const int lr = tid >> 2, lkv = tid & 3;    // row 0-63, chunk 0-3

    auto load_tile = [&](int t, int s) {
        const uint32_t sb = sAddr + s * STAGEB;
        #pragma unroll
        for (int it = 0; it < 2; ++it) {
            int r = lr + it * 64;
            const __nv_bfloat16* ar = A + (size_t)(m0 + r) * KTOT + t * TK;
            const __nv_bfloat16* br = B + (size_t)(n0 + r) * KTOT + t * TK;
            #pragma unroll
            for (int c2 = 0; c2 < 2; ++c2) {
                int ch = lkv + c2 * 4;
                cp16(sb + r * AST + ch * 16, ar + ch * 8);
                cp16(sb + HALFB + r * AST + ch * 16, br + ch * 8);
            }
        }
    };

    load_tile(0, 0); CP_COMMIT();
    load_tile(1, 1); CP_COMMIT();

    float acc[4][4][4];
    #pragma unroll
    for (int i = 0; i < 4; ++i)
        #pragma unroll
        for (int j = 0; j < 4; ++j)
            #pragma unroll
            for (int k = 0; k < 4; ++k) acc[i][j][k] = 0.0f;

    const uint32_t aLane =
        (uint32_t)(warp_m * 64 + (lane & 15)) * AST + (lane >> 4) * 16;
    const uint32_t bLane = HALFB +
        (uint32_t)(warp_n * 32 + ((lane & 7) | ((lane & 16) >> 1))) * AST +
        ((lane >> 3) & 1) * 16;

    for (int t = 0; t < NT; ++t) {
        CP_WAIT1();
        __syncthreads();
        const int buf = t & 1;
        const uint32_t base = sAddr + buf * STAGEB;
        #pragma unroll
        for (int ks = 0; ks < 4; ++ks) {
            uint32_t af[4][4], bf[2][4];
            #pragma unroll
            for (int fm = 0; fm < 4; ++fm)
                ldsm4(af[fm], base + aLane + fm * (16 * AST) + ks * 32);
            #pragma unroll
            for (int fp = 0; fp < 2; ++fp)
                ldsm4(bf[fp], base + bLane + fp * (16 * AST) + ks * 32);
            #pragma unroll
            for (int fm = 0; fm < 4; ++fm)
                #pragma unroll
                for (int fn = 0; fn < 4; ++fn)
                    mma_bf16(acc[fm][fn], af[fm], &bf[fn >> 1][(fn & 1) * 2]);
        }
        __syncthreads();
        if (t + 2 < NT) load_tile(t + 2, buf);
        CP_COMMIT();
    }

    // -------- epilogue -------------------------------------------------------
    float* __restrict__ O = G1 ? g_h : outp;
    float lmax = 0.0f;
    #pragma unroll
    for (int fm = 0; fm < 4; ++fm) {
        const int r0 = m0 + warp_m * 64 + fm * 16 + (lane >> 2);
        #pragma unroll
        for (int fn = 0; fn < 4; ++fn) {
            const int cl = warp_n * 32 + fn * 8 + (lane & 3) * 2;
            const float s0 = csc[cl], s1 = csc[cl + 1];
            const float d0 = cbd[cl], d1 = cbd[cl + 1];
            float v00 = s0 * acc[fm][fn][0] + d0;
            float v01 = s1 * acc[fm][fn][1] + d1;
            float v10 = s0 * acc[fm][fn][2] + d0;
            float v11 = s1 * acc[fm][fn][3] + d1;
            if (G1) {
                v00 = fmaxf(v00, 0.0f); v01 = fmaxf(v01, 0.0f);
                v10 = fmaxf(v10, 0.0f); v11 = fmaxf(v11, 0.0f);
                lmax = fmaxf(lmax, fmaxf(fmaxf(v00, v01), fmaxf(v10, v11)));
            }
            *reinterpret_cast<float2*>(O + (size_t)r0 * NTOT + n0 + cl) =
                make_float2(v00, v01);
            *reinterpret_cast<float2*>(O + (size_t)(r0 + 8) * NTOT + n0 + cl) =
                make_float2(v10, v11);
        }
    }

    if (G1) {
        #pragma unroll
        for (int o = 16; o; o >>= 1) lmax = fmaxf(lmax, __shfl_xor_sync(0xffffffffu, lmax, o));
        if (lane == 0) wred[wid] = lmax;
        __syncthreads();
        if (tid == 0) {
            float b = wred[0];
            #pragma unroll
            for (int i = 1; i < 8; i++) b = fmaxf(b, wred[i]);
            atomicMax(reinterpret_cast<unsigned int*>(&g_maxh), __float_as_uint(b));
        }
    }
}

// ---------------- launcher ---------------------------------------------------
extern "C" void kernel_launch(void* const* d_in, const int* in_sizes, int n_in,
                              void* d_out, int out_size)
{
    const float* x  = (const float*)d_in[0];
    const float* w1 = (const float*)d_in[1];
    const float* b1 = (const float*)d_in[2];
    const float* w2 = (const float*)d_in[3];
    const float* b2 = (const float*)d_in[4];
    float* out = (float*)d_out;

    __nv_bfloat16* qw1p; cudaGetSymbolAddress((void**)&qw1p, g_qw1);
    __nv_bfloat16* qw2p; cudaGetSymbolAddress((void**)&qw2p, g_qw2);
    float* sw1p;  cudaGetSymbolAddress((void**)&sw1p, g_sw1);
    float* sw2p;  cudaGetSymbolAddress((void**)&sw2p, g_sw2);

    cudaFuncSetAttribute((const void*)gemm_hmma<D_DIM, F_DIM, true>,
                         cudaFuncAttributeMaxDynamicSharedMemorySize, GEMM_SMEM);
    cudaFuncSetAttribute((const void*)gemm_hmma<F_DIM, D_DIM, false>,
                         cudaFuncAttributeMaxDynamicSharedMemorySize, GEMM_SMEM);

    init_kernel<<<1, 1>>>();
    max_x_kernel<<<256, 256>>>(x);
    scales_w_kernel<D_DIM, true><<<F_DIM, 128>>>(w1, b1);
    scales_w_kernel<F_DIM, false><<<D_DIM, 128>>>(w2, nullptr);
    quant_w_kernel<D_DIM><<<512, 256>>>(w1, sw1p, qw1p, F_DIM * D_DIM);
    quant_w_kernel<F_DIM><<<512, 256>>>(w2, sw2p, qw2p, D_DIM * F_DIM);
    quant_x_kernel<<<1024, 256>>>(x);
    gemm_hmma<D_DIM, F_DIM, true>
        <<<dim3(F_DIM / TN, M_TOT / TM), 256, GEMM_SMEM>>>(nullptr, nullptr);
    quant_h_kernel<<<2048, 256>>>();
    gemm_hmma<F_DIM, D_DIM, false>
        <<<dim3(D_DIM / TN, M_TOT / TM), 256, GEMM_SMEM>>>(out, b2);
}

// round 5
// speedup vs baseline: 2.0823x; 1.6217x over previous
#include <cuda_runtime.h>
#include <cuda_bf16.h>
#include <cstdint>
#include <cstddef>

// ============================================================================
// Quantized FFN via exact integer-in-bf16 GEMMs:
//   out = quant_linear(relu(quant_linear(x, w1, b1)), w2, b2)
// R5: 128x256 CTA tile / 64x64 warp tile, 3-stage cp.async, 1 sync per K-tile.
// ============================================================================

#define EPSQ 1e-8f

static constexpr int M_TOT = 8192;
static constexpr int D_DIM = 1024;
static constexpr int F_DIM = 4096;

// ---------------- scratch ----------------------------------------------------
__device__ float g_maxx;
__device__ float g_maxh;
__device__ __nv_bfloat16 g_qx[(size_t)M_TOT * D_DIM];
__device__ __nv_bfloat16 g_qw1[(size_t)F_DIM * D_DIM];
__device__ float g_scale1[F_DIM];
__device__ float g_badd1[F_DIM];
__device__ __nv_bfloat16 g_qw2[(size_t)D_DIM * F_DIM];
__device__ float g_sw2[D_DIM];
__device__ float g_h[(size_t)M_TOT * F_DIM];
__device__ __nv_bfloat16 g_qh[(size_t)M_TOT * F_DIM];

// ---------------- PTX helpers ------------------------------------------------
__device__ __forceinline__ uint32_t smem_u32(const void* p) {
    uint32_t a;
    asm("{ .reg .u64 t; cvta.to.shared.u64 t, %1; cvt.u32.u64 %0, t; }"
        : "=r"(a) : "l"(p));
    return a;
}

__device__ __forceinline__ void cp16(uint32_t dst, const void* src) {
    asm volatile("cp.async.cg.shared.global [%0], [%1], 16;" :: "r"(dst), "l"(src));
}
#define CP_COMMIT() asm volatile("cp.async.commit_group;" ::: "memory")
#define CP_WAIT1()  asm volatile("cp.async.wait_group 1;" ::: "memory")

__device__ __forceinline__ void ldsm4(uint32_t* r, uint32_t addr) {
    asm volatile("ldmatrix.sync.aligned.m8n8.x4.shared.b16 {%0,%1,%2,%3}, [%4];"
        : "=r"(r[0]), "=r"(r[1]), "=r"(r[2]), "=r"(r[3]) : "r"(addr));
}

__device__ __forceinline__ void mma_bf16(float* c, const uint32_t* a, const uint32_t* b) {
    asm volatile(
        "mma.sync.aligned.m16n8k16.row.col.f32.bf16.bf16.f32 "
        "{%0,%1,%2,%3}, {%4,%5,%6,%7}, {%8,%9}, {%0,%1,%2,%3};"
        : "+f"(c[0]), "+f"(c[1]), "+f"(c[2]), "+f"(c[3])
        : "r"(a[0]), "r"(a[1]), "r"(a[2]), "r"(a[3]), "r"(b[0]), "r"(b[1]));
}

// ---------------- elementwise / reduction kernels ----------------------------
__global__ void init_kernel() {
    g_maxx = 0.0f;
    g_maxh = 0.0f;
}

__global__ void max_x_kernel(const float* __restrict__ x) {
    float m = 0.0f;
    const int n4 = (M_TOT * D_DIM) / 4;
    for (int i = blockIdx.x * blockDim.x + threadIdx.x; i < n4; i += gridDim.x * blockDim.x) {
        float4 v = reinterpret_cast<const float4*>(x)[i];
        m = fmaxf(m, fmaxf(fmaxf(v.x, v.y), fmaxf(v.z, v.w)));
    }
    #pragma unroll
    for (int o = 16; o; o >>= 1) m = fmaxf(m, __shfl_xor_sync(0xffffffffu, m, o));
    __shared__ float red[8];
    int wid = threadIdx.x >> 5, lid = threadIdx.x & 31;
    if (lid == 0) red[wid] = m;
    __syncthreads();
    if (threadIdx.x == 0) {
        float b = red[0];
        int nw = blockDim.x >> 5;
        for (int i = 1; i < nw; i++) b = fmaxf(b, red[i]);
        atomicMax(reinterpret_cast<unsigned int*>(&g_maxx), __float_as_uint(fmaxf(b, 0.0f)));
    }
}

// fused per-row scale + quantize (row stays in registers); 256 threads/row
template <int K, bool W1>
__global__ void quantw_fused(const float* __restrict__ w, const float* __restrict__ b1,
                             __nv_bfloat16* __restrict__ qw) {
    constexpr int NV = K / 1024;  // float4 per thread
    const int r = blockIdx.x;
    const int t = threadIdx.x;
    const float4* row = reinterpret_cast<const float4*>(w + (size_t)r * K);
    float4 v[NV];
    float m = 0.0f;
    #pragma unroll
    for (int i = 0; i < NV; ++i) {
        v[i] = row[t + i * 256];
        m = fmaxf(m, fmaxf(fmaxf(fabsf(v[i].x), fabsf(v[i].y)),
                           fmaxf(fabsf(v[i].z), fabsf(v[i].w))));
    }
    #pragma unroll
    for (int o = 16; o; o >>= 1) m = fmaxf(m, __shfl_xor_sync(0xffffffffu, m, o));
    __shared__ float red[8];
    __shared__ float s_sh;
    if ((t & 31) == 0) red[t >> 5] = m;
    __syncthreads();
    if (t == 0) {
        float b = red[0];
        #pragma unroll
        for (int i = 1; i < 8; ++i) b = fmaxf(b, red[i]);
        float s = __fdiv_rn(fmaxf(b, EPSQ), 127.0f);
        s_sh = s;
        if (W1) {
            float s1 = __fdiv_rn(fmaxf(g_maxx, EPSQ), 255.0f);
            float sc = s1 * s;
            g_scale1[r] = sc;
            g_badd1[r] = rintf(__fdiv_rn(b1[r], sc)) * sc;
        } else {
            g_sw2[r] = s;
        }
    }
    __syncthreads();
    const float s = s_sh;
    #pragma unroll
    for (int i = 0; i < NV; ++i) {
        float q0 = fminf(fmaxf(rintf(__fdiv_rn(v[i].x, s)), -128.0f), 127.0f);
        float q1 = fminf(fmaxf(rintf(__fdiv_rn(v[i].y, s)), -128.0f), 127.0f);
        float q2 = fminf(fmaxf(rintf(__fdiv_rn(v[i].z, s)), -128.0f), 127.0f);
        float q3 = fminf(fmaxf(rintf(__fdiv_rn(v[i].w, s)), -128.0f), 127.0f);
        __nv_bfloat162 lo = __floats2bfloat162_rn(q0, q1);
        __nv_bfloat162 hi = __floats2bfloat162_rn(q2, q3);
        uint2 pk;
        pk.x = *reinterpret_cast<unsigned int*>(&lo);
        pk.y = *reinterpret_cast<unsigned int*>(&hi);
        reinterpret_cast<uint2*>(qw)[((size_t)r * K) / 4 + t + i * 256] = pk;
    }
}

__global__ void quant_x_kernel(const float* __restrict__ x) {
    const float s1 = __fdiv_rn(fmaxf(g_maxx, EPSQ), 255.0f);
    const int n4 = (M_TOT * D_DIM) / 4;
    for (int i = blockIdx.x * blockDim.x + threadIdx.x; i < n4; i += gridDim.x * blockDim.x) {
        float4 v = reinterpret_cast<const float4*>(x)[i];
        float q0 = fminf(fmaxf(rintf(__fdiv_rn(v.x, s1)), 0.0f), 255.0f);
        float q1 = fminf(fmaxf(rintf(__fdiv_rn(v.y, s1)), 0.0f), 255.0f);
        float q2 = fminf(fmaxf(rintf(__fdiv_rn(v.z, s1)), 0.0f), 255.0f);
        float q3 = fminf(fmaxf(rintf(__fdiv_rn(v.w, s1)), 0.0f), 255.0f);
        __nv_bfloat162 lo = __floats2bfloat162_rn(q0, q1);
        __nv_bfloat162 hi = __floats2bfloat162_rn(q2, q3);
        uint2 pk;
        pk.x = *reinterpret_cast<unsigned int*>(&lo);
        pk.y = *reinterpret_cast<unsigned int*>(&hi);
        reinterpret_cast<uint2*>(g_qx)[i] = pk;
    }
}

__global__ void quant_h_kernel() {
    const float s2 = __fdiv_rn(fmaxf(g_maxh, EPSQ), 255.0f);
    const size_t n4 = ((size_t)M_TOT * F_DIM) / 4;
    for (size_t i = blockIdx.x * (size_t)blockDim.x + threadIdx.x; i < n4;
         i += (size_t)gridDim.x * blockDim.x) {
        float4 v = reinterpret_cast<const float4*>(g_h)[i];
        float q0 = fminf(fmaxf(rintf(__fdiv_rn(v.x, s2)), 0.0f), 255.0f);
        float q1 = fminf(fmaxf(rintf(__fdiv_rn(v.y, s2)), 0.0f), 255.0f);
        float q2 = fminf(fmaxf(rintf(__fdiv_rn(v.z, s2)), 0.0f), 255.0f);
        float q3 = fminf(fmaxf(rintf(__fdiv_rn(v.w, s2)), 0.0f), 255.0f);
        __nv_bfloat162 lo = __floats2bfloat162_rn(q0, q1);
        __nv_bfloat162 hi = __floats2bfloat162_rn(q2, q3);
        uint2 pk;
        pk.x = *reinterpret_cast<unsigned int*>(&lo);
        pk.y = *reinterpret_cast<unsigned int*>(&hi);
        reinterpret_cast<uint2*>(g_qh)[i] = pk;
    }
}

// ---------------- bf16 GEMM --------------------------------------------------
// CTA 128(M) x 256(N) x 64(K); 8 warps 2(M)x4(N); warp 64x64; m16n8k16.
// 3-stage cp.async pipeline, one __syncthreads per K-tile.
static constexpr int TM = 128, TN = 256, TK = 64;
static constexpr int AST = 144;                  // 128B row + 16B pad
static constexpr int ABYTES = TM * AST;          // 18432
static constexpr int BBYTES = TN * AST;          // 36864
static constexpr int STAGEB = ABYTES + BBYTES;   // 55296
static constexpr int NSTAGE = 3;
static constexpr int GEMM_SMEM = NSTAGE * STAGEB;  // 165888

template <int KTOT, int NTOT, bool G1>
__global__ void __launch_bounds__(256, 1) gemm_hmma(float* __restrict__ outp,
                                                    const float* __restrict__ bias)
{
    extern __shared__ __align__(16) unsigned char smem[];
    __shared__ float csc[TN], cbd[TN], wred[8];

    const int tid = threadIdx.x, lane = tid & 31, wid = tid >> 5;
    const int warp_m = wid & 1, warp_n = wid >> 1;
    const int m0 = blockIdx.y * TM, n0 = blockIdx.x * TN;

    const __nv_bfloat16* __restrict__ A = G1 ? g_qx : g_qh;
    const __nv_bfloat16* __restrict__ B = G1 ? g_qw1 : g_qw2;

    {
        int n = n0 + tid;
        if (G1) {
            csc[tid] = g_scale1[n];
            cbd[tid] = g_badd1[n];
        } else {
            float s2 = __fdiv_rn(fmaxf(g_maxh, EPSQ), 255.0f);
            float sc = s2 * g_sw2[n];
            csc[tid] = sc;
            cbd[tid] = rintf(__fdiv_rn(bias[n], sc)) * sc;
        }
    }

    const uint32_t sAddr = smem_u32(smem);
    const int NT = KTOT / TK;

    auto load_tile = [&](int t, int s) {
        const uint32_t sb = sAddr + s * STAGEB;
        const int kb = t * TK;
        #pragma unroll
        for (int it = 0; it < 4; ++it) {          // A: 128 rows x 8 chunks
            int i = tid + it * 256;
            int r = i >> 3, ch = i & 7;
            cp16(sb + r * AST + ch * 16, A + (size_t)(m0 + r) * KTOT + kb + ch * 8);
        }
        #pragma unroll
        for (int it = 0; it < 8; ++it) {          // B: 256 rows x 8 chunks
            int i = tid + it * 256;
            int r = i >> 3, ch = i & 7;
            cp16(sb + ABYTES + r * AST + ch * 16, B + (size_t)(n0 + r) * KTOT + kb + ch * 8);
        }
    };

    load_tile(0, 0); CP_COMMIT();
    load_tile(1, 1); CP_COMMIT();

    float acc[4][8][4];
    #pragma unroll
    for (int i = 0; i < 4; ++i)
        #pragma unroll
        for (int j = 0; j < 8; ++j)
            #pragma unroll
            for (int k = 0; k < 4; ++k) acc[i][j][k] = 0.0f;

    const uint32_t aLane =
        (uint32_t)(warp_m * 64 + (lane & 15)) * AST + (lane >> 4) * 16;
    const uint32_t bLane = ABYTES +
        (uint32_t)(warp_n * 64 + ((lane & 7) | ((lane & 16) >> 1))) * AST +
        ((lane >> 3) & 1) * 16;

    int buf = 0;
    for (int t = 0; t < NT; ++t) {
        CP_WAIT1();
        __syncthreads();
        if (t + 2 < NT) {
            int s = buf + 2; if (s >= NSTAGE) s -= NSTAGE;
            load_tile(t + 2, s);
        }
        CP_COMMIT();

        const uint32_t base = sAddr + buf * STAGEB;
        #pragma unroll
        for (int ks = 0; ks < 4; ++ks) {
            uint32_t af[4][4], bf[4][4];
            #pragma unroll
            for (int fm = 0; fm < 4; ++fm)
                ldsm4(af[fm], base + aLane + fm * (16 * AST) + ks * 32);
            #pragma unroll
            for (int fp = 0; fp < 4; ++fp)
                ldsm4(bf[fp], base + bLane + fp * (16 * AST) + ks * 32);
            #pragma unroll
            for (int fm = 0; fm < 4; ++fm)
                #pragma unroll
                for (int fn = 0; fn < 8; ++fn)
                    mma_bf16(acc[fm][fn], af[fm], &bf[fn >> 1][(fn & 1) * 2]);
        }
        if (++buf == NSTAGE) buf = 0;
    }

    // -------- epilogue -------------------------------------------------------
    float* __restrict__ O = G1 ? g_h : outp;
    float lmax = 0.0f;
    #pragma unroll
    for (int fm = 0; fm < 4; ++fm) {
        const int r0 = m0 + warp_m * 64 + fm * 16 + (lane >> 2);
        #pragma unroll
        for (int fn = 0; fn < 8; ++fn) {
            const int cl = warp_n * 64 + fn * 8 + (lane & 3) * 2;
            const float s0 = csc[cl], s1 = csc[cl + 1];
            const float d0 = cbd[cl], d1 = cbd[cl + 1];
            float v00 = s0 * acc[fm][fn][0] + d0;
            float v01 = s1 * acc[fm][fn][1] + d1;
            float v10 = s0 * acc[fm][fn][2] + d0;
            float v11 = s1 * acc[fm][fn][3] + d1;
            if (G1) {
                v00 = fmaxf(v00, 0.0f); v01 = fmaxf(v01, 0.0f);
                v10 = fmaxf(v10, 0.0f); v11 = fmaxf(v11, 0.0f);
                lmax = fmaxf(lmax, fmaxf(fmaxf(v00, v01), fmaxf(v10, v11)));
            }
            *reinterpret_cast<float2*>(O + (size_t)r0 * NTOT + n0 + cl) =
                make_float2(v00, v01);
            *reinterpret_cast<float2*>(O + (size_t)(r0 + 8) * NTOT + n0 + cl) =
                make_float2(v10, v11);
        }
    }

    if (G1) {
        #pragma unroll
        for (int o = 16; o; o >>= 1) lmax = fmaxf(lmax, __shfl_xor_sync(0xffffffffu, lmax, o));
        if (lane == 0) wred[wid] = lmax;
        __syncthreads();
        if (tid == 0) {
            float b = wred[0];
            #pragma unroll
            for (int i = 1; i < 8; i++) b = fmaxf(b, wred[i]);
            atomicMax(reinterpret_cast<unsigned int*>(&g_maxh), __float_as_uint(b));
        }
    }
}

// ---------------- launcher ---------------------------------------------------
extern "C" void kernel_launch(void* const* d_in, const int* in_sizes, int n_in,
                              void* d_out, int out_size)
{
    const float* x  = (const float*)d_in[0];
    const float* w1 = (const float*)d_in[1];
    const float* b1 = (const float*)d_in[2];
    const float* w2 = (const float*)d_in[3];
    const float* b2 = (const float*)d_in[4];
    float* out = (float*)d_out;

    __nv_bfloat16* qw1p; cudaGetSymbolAddress((void**)&qw1p, g_qw1);
    __nv_bfloat16* qw2p; cudaGetSymbolAddress((void**)&qw2p, g_qw2);

    cudaFuncSetAttribute((const void*)gemm_hmma<D_DIM, F_DIM, true>,
                         cudaFuncAttributeMaxDynamicSharedMemorySize, GEMM_SMEM);
    cudaFuncSetAttribute((const void*)gemm_hmma<F_DIM, D_DIM, false>,
                         cudaFuncAttributeMaxDynamicSharedMemorySize, GEMM_SMEM);

    init_kernel<<<1, 1>>>();
    max_x_kernel<<<256, 256>>>(x);
    quantw_fused<D_DIM, true><<<F_DIM, 256>>>(w1, b1, qw1p);
    quantw_fused<F_DIM, false><<<D_DIM, 256>>>(w2, nullptr, qw2p);
    quant_x_kernel<<<1024, 256>>>(x);
    gemm_hmma<D_DIM, F_DIM, true>
        <<<dim3(F_DIM / TN, M_TOT / TM), 256, GEMM_SMEM>>>(nullptr, nullptr);
    quant_h_kernel<<<2048, 256>>>();
    gemm_hmma<F_DIM, D_DIM, false>
        <<<dim3(D_DIM / TN, M_TOT / TM), 256, GEMM_SMEM>>>(out, b2);
}

// round 6
// speedup vs baseline: 2.2511x; 1.0810x over previous
#include <cuda_runtime.h>
#include <cuda_bf16.h>
#include <cstdint>
#include <cstddef>

// ============================================================================
// Quantized FFN via exact integer-in-bf16 GEMMs:
//   out = quant_linear(relu(quant_linear(x, w1, b1)), w2, b2)
// R6: reciprocal-multiply quantization (no per-element FDIV), wide streaming
// grids, 4-stage cp.async GEMM pipeline.
// ============================================================================

#define EPSQ 1e-8f

static constexpr int M_TOT = 8192;
static constexpr int D_DIM = 1024;
static constexpr int F_DIM = 4096;
static constexpr int SGRID = 1184;   // 8 * 148 SMs

// ---------------- scratch ----------------------------------------------------
__device__ float g_maxx;
__device__ float g_maxh;
__device__ __nv_bfloat16 g_qx[(size_t)M_TOT * D_DIM];
__device__ __nv_bfloat16 g_qw1[(size_t)F_DIM * D_DIM];
__device__ float g_scale1[F_DIM];
__device__ float g_badd1[F_DIM];
__device__ __nv_bfloat16 g_qw2[(size_t)D_DIM * F_DIM];
__device__ float g_sw2[D_DIM];
__device__ float g_h[(size_t)M_TOT * F_DIM];
__device__ __nv_bfloat16 g_qh[(size_t)M_TOT * F_DIM];

// ---------------- PTX helpers ------------------------------------------------
__device__ __forceinline__ uint32_t smem_u32(const void* p) {
    uint32_t a;
    asm("{ .reg .u64 t; cvta.to.shared.u64 t, %1; cvt.u32.u64 %0, t; }"
        : "=r"(a) : "l"(p));
    return a;
}

__device__ __forceinline__ void cp16(uint32_t dst, const void* src) {
    asm volatile("cp.async.cg.shared.global [%0], [%1], 16;" :: "r"(dst), "l"(src));
}
#define CP_COMMIT() asm volatile("cp.async.commit_group;" ::: "memory")
#define CP_WAIT2()  asm volatile("cp.async.wait_group 2;" ::: "memory")

__device__ __forceinline__ void ldsm4(uint32_t* r, uint32_t addr) {
    asm volatile("ldmatrix.sync.aligned.m8n8.x4.shared.b16 {%0,%1,%2,%3}, [%4];"
        : "=r"(r[0]), "=r"(r[1]), "=r"(r[2]), "=r"(r[3]) : "r"(addr));
}

__device__ __forceinline__ void mma_bf16(float* c, const uint32_t* a, const uint32_t* b) {
    asm volatile(
        "mma.sync.aligned.m16n8k16.row.col.f32.bf16.bf16.f32 "
        "{%0,%1,%2,%3}, {%4,%5,%6,%7}, {%8,%9}, {%0,%1,%2,%3};"
        : "+f"(c[0]), "+f"(c[1]), "+f"(c[2]), "+f"(c[3])
        : "r"(a[0]), "r"(a[1]), "r"(a[2]), "r"(a[3]), "r"(b[0]), "r"(b[1]));
}

__device__ __forceinline__ uint2 quant_pack4(float4 v, float rs, float lo, float hi) {
    float q0 = fminf(fmaxf(rintf(v.x * rs), lo), hi);
    float q1 = fminf(fmaxf(rintf(v.y * rs), lo), hi);
    float q2 = fminf(fmaxf(rintf(v.z * rs), lo), hi);
    float q3 = fminf(fmaxf(rintf(v.w * rs), lo), hi);
    __nv_bfloat162 l = __floats2bfloat162_rn(q0, q1);
    __nv_bfloat162 h = __floats2bfloat162_rn(q2, q3);
    uint2 pk;
    pk.x = *reinterpret_cast<unsigned int*>(&l);
    pk.y = *reinterpret_cast<unsigned int*>(&h);
    return pk;
}

// ---------------- elementwise / reduction kernels ----------------------------
__global__ void init_kernel() {
    g_maxx = 0.0f;
    g_maxh = 0.0f;
}

__global__ void max_x_kernel(const float* __restrict__ x) {
    float m = 0.0f;
    const int n4 = (M_TOT * D_DIM) / 4;
    const int stride = gridDim.x * blockDim.x;
    int i = blockIdx.x * blockDim.x + threadIdx.x;
    #pragma unroll 4
    for (; i < n4; i += stride) {
        float4 v = reinterpret_cast<const float4*>(x)[i];
        m = fmaxf(m, fmaxf(fmaxf(v.x, v.y), fmaxf(v.z, v.w)));
    }
    #pragma unroll
    for (int o = 16; o; o >>= 1) m = fmaxf(m, __shfl_xor_sync(0xffffffffu, m, o));
    __shared__ float red[8];
    int wid = threadIdx.x >> 5, lid = threadIdx.x & 31;
    if (lid == 0) red[wid] = m;
    __syncthreads();
    if (threadIdx.x == 0) {
        float b = red[0];
        int nw = blockDim.x >> 5;
        for (int i2 = 1; i2 < nw; i2++) b = fmaxf(b, red[i2]);
        atomicMax(reinterpret_cast<unsigned int*>(&g_maxx), __float_as_uint(fmaxf(b, 0.0f)));
    }
}

// fused per-row scale + quantize (row held in registers); 256 threads/row
template <int K, bool W1>
__global__ void quantw_fused(const float* __restrict__ w, const float* __restrict__ b1,
                             __nv_bfloat16* __restrict__ qw) {
    constexpr int NV = K / 1024;  // float4 per thread
    const int r = blockIdx.x;
    const int t = threadIdx.x;
    const float4* row = reinterpret_cast<const float4*>(w + (size_t)r * K);
    float4 v[NV];
    float m = 0.0f;
    #pragma unroll
    for (int i = 0; i < NV; ++i) {
        v[i] = row[t + i * 256];
        m = fmaxf(m, fmaxf(fmaxf(fabsf(v[i].x), fabsf(v[i].y)),
                           fmaxf(fabsf(v[i].z), fabsf(v[i].w))));
    }
    #pragma unroll
    for (int o = 16; o; o >>= 1) m = fmaxf(m, __shfl_xor_sync(0xffffffffu, m, o));
    __shared__ float red[8];
    __shared__ float rs_sh;
    if ((t & 31) == 0) red[t >> 5] = m;
    __syncthreads();
    if (t == 0) {
        float b = red[0];
        #pragma unroll
        for (int i = 1; i < 8; ++i) b = fmaxf(b, red[i]);
        float s = __fdiv_rn(fmaxf(b, EPSQ), 127.0f);
        rs_sh = __fdiv_rn(1.0f, s);
        if (W1) {
            float s1 = __fdiv_rn(fmaxf(g_maxx, EPSQ), 255.0f);
            float sc = s1 * s;
            g_scale1[r] = sc;
            g_badd1[r] = rintf(__fdiv_rn(b1[r], sc)) * sc;
        } else {
            g_sw2[r] = s;
        }
    }
    __syncthreads();
    const float rs = rs_sh;
    #pragma unroll
    for (int i = 0; i < NV; ++i)
        reinterpret_cast<uint2*>(qw)[((size_t)r * K) / 4 + t + i * 256] =
            quant_pack4(v[i], rs, -128.0f, 127.0f);
}

__global__ void quant_x_kernel(const float* __restrict__ x) {
    const float rs = __fdiv_rn(255.0f, fmaxf(g_maxx, EPSQ));
    const int n4 = (M_TOT * D_DIM) / 4;
    const int stride = gridDim.x * blockDim.x;
    int i = blockIdx.x * blockDim.x + threadIdx.x;
    #pragma unroll 4
    for (; i < n4; i += stride) {
        float4 v = reinterpret_cast<const float4*>(x)[i];
        reinterpret_cast<uint2*>(g_qx)[i] = quant_pack4(v, rs, 0.0f, 255.0f);
    }
}

__global__ void quant_h_kernel() {
    const float rs = __fdiv_rn(255.0f, fmaxf(g_maxh, EPSQ));
    const int n4 = (int)(((size_t)M_TOT * F_DIM) / 4);
    const int stride = gridDim.x * blockDim.x;
    int i = blockIdx.x * blockDim.x + threadIdx.x;
    #pragma unroll 4
    for (; i < n4; i += stride) {
        float4 v = reinterpret_cast<const float4*>(g_h)[i];
        reinterpret_cast<uint2*>(g_qh)[i] = quant_pack4(v, rs, 0.0f, 255.0f);
    }
}

// ---------------- bf16 GEMM --------------------------------------------------
// CTA 128(M) x 256(N) x 64(K); 8 warps 2(M)x4(N); warp 64x64; m16n8k16.
// 4-stage cp.async pipeline, one __syncthreads per K-tile.
static constexpr int TM = 128, TN = 256, TK = 64;
static constexpr int AST = 144;
static constexpr int ABYTES = TM * AST;
static constexpr int BBYTES = TN * AST;
static constexpr int STAGEB = ABYTES + BBYTES;     // 55296
static constexpr int NSTAGE = 4;
static constexpr int GEMM_SMEM = NSTAGE * STAGEB;  // 221184

template <int KTOT, int NTOT, bool G1>
__global__ void __launch_bounds__(256, 1) gemm_hmma(float* __restrict__ outp,
                                                    const float* __restrict__ bias)
{
    extern __shared__ __align__(16) unsigned char smem[];
    __shared__ float csc[TN], cbd[TN], wred[8];

    const int tid = threadIdx.x, lane = tid & 31, wid = tid >> 5;
    const int warp_m = wid & 1, warp_n = wid >> 1;
    const int m0 = blockIdx.y * TM, n0 = blockIdx.x * TN;

    const __nv_bfloat16* __restrict__ A = G1 ? g_qx : g_qh;
    const __nv_bfloat16* __restrict__ B = G1 ? g_qw1 : g_qw2;

    {
        int n = n0 + tid;
        if (G1) {
            csc[tid] = g_scale1[n];
            cbd[tid] = g_badd1[n];
        } else {
            float s2 = __fdiv_rn(fmaxf(g_maxh, EPSQ), 255.0f);
            float sc = s2 * g_sw2[n];
            csc[tid] = sc;
            cbd[tid] = rintf(__fdiv_rn(bias[n], sc)) * sc;
        }
    }

    const uint32_t sAddr = smem_u32(smem);
    const int NT = KTOT / TK;

    auto load_tile = [&](int t, int s) {
        const uint32_t sb = sAddr + s * STAGEB;
        const int kb = t * TK;
        #pragma unroll
        for (int it = 0; it < 4; ++it) {
            int i = tid + it * 256;
            int r = i >> 3, ch = i & 7;
            cp16(sb + r * AST + ch * 16, A + (size_t)(m0 + r) * KTOT + kb + ch * 8);
        }
        #pragma unroll
        for (int it = 0; it < 8; ++it) {
            int i = tid + it * 256;
            int r = i >> 3, ch = i & 7;
            cp16(sb + ABYTES + r * AST + ch * 16, B + (size_t)(n0 + r) * KTOT + kb + ch * 8);
        }
    };

    load_tile(0, 0); CP_COMMIT();
    load_tile(1, 1); CP_COMMIT();
    load_tile(2, 2); CP_COMMIT();

    float acc[4][8][4];
    #pragma unroll
    for (int i = 0; i < 4; ++i)
        #pragma unroll
        for (int j = 0; j < 8; ++j)
            #pragma unroll
            for (int k = 0; k < 4; ++k) acc[i][j][k] = 0.0f;

    const uint32_t aLane =
        (uint32_t)(warp_m * 64 + (lane & 15)) * AST + (lane >> 4) * 16;
    const uint32_t bLane = ABYTES +
        (uint32_t)(warp_n * 64 + ((lane & 7) | ((lane & 16) >> 1))) * AST +
        ((lane >> 3) & 1) * 16;

    int buf = 0;
    for (int t = 0; t < NT; ++t) {
        CP_WAIT2();
        __syncthreads();
        if (t + 3 < NT) {
            int s = buf + 3; if (s >= NSTAGE) s -= NSTAGE;
            load_tile(t + 3, s);
        }
        CP_COMMIT();

        const uint32_t base = sAddr + buf * STAGEB;
        #pragma unroll
        for (int ks = 0; ks < 4; ++ks) {
            uint32_t af[4][4], bf[4][4];
            #pragma unroll
            for (int fm = 0; fm < 4; ++fm)
                ldsm4(af[fm], base + aLane + fm * (16 * AST) + ks * 32);
            #pragma unroll
            for (int fp = 0; fp < 4; ++fp)
                ldsm4(bf[fp], base + bLane + fp * (16 * AST) + ks * 32);
            #pragma unroll
            for (int fm = 0; fm < 4; ++fm)
                #pragma unroll
                for (int fn = 0; fn < 8; ++fn)
                    mma_bf16(acc[fm][fn], af[fm], &bf[fn >> 1][(fn & 1) * 2]);
        }
        if (++buf == NSTAGE) buf = 0;
    }

    // -------- epilogue -------------------------------------------------------
    float* __restrict__ O = G1 ? g_h : outp;
    float lmax = 0.0f;
    #pragma unroll
    for (int fm = 0; fm < 4; ++fm) {
        const int r0 = m0 + warp_m * 64 + fm * 16 + (lane >> 2);
        #pragma unroll
        for (int fn = 0; fn < 8; ++fn) {
            const int cl = warp_n * 64 + fn * 8 + (lane & 3) * 2;
            const float s0 = csc[cl], s1 = csc[cl + 1];
            const float d0 = cbd[cl], d1 = cbd[cl + 1];
            float v00 = s0 * acc[fm][fn][0] + d0;
            float v01 = s1 * acc[fm][fn][1] + d1;
            float v10 = s0 * acc[fm][fn][2] + d0;
            float v11 = s1 * acc[fm][fn][3] + d1;
            if (G1) {
                v00 = fmaxf(v00, 0.0f); v01 = fmaxf(v01, 0.0f);
                v10 = fmaxf(v10, 0.0f); v11 = fmaxf(v11, 0.0f);
                lmax = fmaxf(lmax, fmaxf(fmaxf(v00, v01), fmaxf(v10, v11)));
            }
            *reinterpret_cast<float2*>(O + (size_t)r0 * NTOT + n0 + cl) =
                make_float2(v00, v01);
            *reinterpret_cast<float2*>(O + (size_t)(r0 + 8) * NTOT + n0 + cl) =
                make_float2(v10, v11);
        }
    }

    if (G1) {
        #pragma unroll
        for (int o = 16; o; o >>= 1) lmax = fmaxf(lmax, __shfl_xor_sync(0xffffffffu, lmax, o));
        if (lane == 0) wred[wid] = lmax;
        __syncthreads();
        if (tid == 0) {
            float b = wred[0];
            #pragma unroll
            for (int i = 1; i < 8; i++) b = fmaxf(b, wred[i]);
            atomicMax(reinterpret_cast<unsigned int*>(&g_maxh), __float_as_uint(b));
        }
    }
}

// ---------------- launcher ---------------------------------------------------
extern "C" void kernel_launch(void* const* d_in, const int* in_sizes, int n_in,
                              void* d_out, int out_size)
{
    const float* x  = (const float*)d_in[0];
    const float* w1 = (const float*)d_in[1];
    const float* b1 = (const float*)d_in[2];
    const float* w2 = (const float*)d_in[3];
    const float* b2 = (const float*)d_in[4];
    float* out = (float*)d_out;

    __nv_bfloat16* qw1p; cudaGetSymbolAddress((void**)&qw1p, g_qw1);
    __nv_bfloat16* qw2p; cudaGetSymbolAddress((void**)&qw2p, g_qw2);

    cudaFuncSetAttribute((const void*)gemm_hmma<D_DIM, F_DIM, true>,
                         cudaFuncAttributeMaxDynamicSharedMemorySize, GEMM_SMEM);
    cudaFuncSetAttribute((const void*)gemm_hmma<F_DIM, D_DIM, false>,
                         cudaFuncAttributeMaxDynamicSharedMemorySize, GEMM_SMEM);

    init_kernel<<<1, 1>>>();
    max_x_kernel<<<SGRID, 256>>>(x);
    quantw_fused<D_DIM, true><<<F_DIM, 256>>>(w1, b1, qw1p);
    quantw_fused<F_DIM, false><<<D_DIM, 256>>>(w2, nullptr, qw2p);
    quant_x_kernel<<<SGRID, 256>>>(x);
    gemm_hmma<D_DIM, F_DIM, true>
        <<<dim3(F_DIM / TN, M_TOT / TM), 256, GEMM_SMEM>>>(nullptr, nullptr);
    quant_h_kernel<<<SGRID, 256>>>();
    gemm_hmma<F_DIM, D_DIM, false>
        <<<dim3(D_DIM / TN, M_TOT / TM), 256, GEMM_SMEM>>>(out, b2);
}